// round 1
// baseline (speedup 1.0000x reference)
#include <cuda_runtime.h>
#include <math.h>

#define BB 2
#define SS 2048
#define HID 1024
#define NH 16
#define HD 64
#define M_TOK (BB*SS)                       // 4096
#define CTX_ELEMS ((size_t)BB*SS*HID)       // 4194304

// Scratch for head-split Q,K,V: [B, NH, S, HD]
__device__ float g_q[BB*NH*SS*HD];
__device__ float g_k[BB*NH*SS*HD];
__device__ float g_v[BB*NH*SS*HD];

// ---------------------------------------------------------------------------
// QKV projection: out[m,n] = sum_k hidden[m,k] * W[n,k] + bias[n]
// Written directly in head-split layout [B,NH,S,HD].
// Classic 128x128x8 fp32 SGEMM, 256 threads, 8x8 per thread.
// ---------------------------------------------------------------------------
__global__ __launch_bounds__(256) void qkv_gemm(const float* __restrict__ A,
                                                const float* __restrict__ W,
                                                const float* __restrict__ bias,
                                                int which) {
    __shared__ float As[8][128];
    __shared__ float Ws[8][128];
    float* outbuf = (which == 0) ? g_q : (which == 1) ? g_k : g_v;

    int tid = threadIdx.x;
    int m0 = blockIdx.y * 128;
    int n0 = blockIdx.x * 128;
    int tx = tid & 15, ty = tid >> 4;
    int lrow = tid >> 1;          // 0..127
    int lcol = (tid & 1) * 4;     // 0 or 4

    float acc[8][8];
#pragma unroll
    for (int i = 0; i < 8; i++)
#pragma unroll
        for (int j = 0; j < 8; j++) acc[i][j] = 0.f;

    for (int k0 = 0; k0 < HID; k0 += 8) {
        float4 av = *(const float4*)(A + (size_t)(m0 + lrow) * HID + k0 + lcol);
        As[lcol + 0][lrow] = av.x; As[lcol + 1][lrow] = av.y;
        As[lcol + 2][lrow] = av.z; As[lcol + 3][lrow] = av.w;
        float4 wv = *(const float4*)(W + (size_t)(n0 + lrow) * HID + k0 + lcol);
        Ws[lcol + 0][lrow] = wv.x; Ws[lcol + 1][lrow] = wv.y;
        Ws[lcol + 2][lrow] = wv.z; Ws[lcol + 3][lrow] = wv.w;
        __syncthreads();
#pragma unroll
        for (int kk = 0; kk < 8; kk++) {
            float a[8], b[8];
#pragma unroll
            for (int i = 0; i < 8; i++) a[i] = As[kk][ty * 8 + i];
#pragma unroll
            for (int j = 0; j < 8; j++) b[j] = Ws[kk][tx * 8 + j];
#pragma unroll
            for (int i = 0; i < 8; i++)
#pragma unroll
                for (int j = 0; j < 8; j++) acc[i][j] += a[i] * b[j];
        }
        __syncthreads();
    }

#pragma unroll
    for (int i = 0; i < 8; i++) {
        int m = m0 + ty * 8 + i;
        int b_ = m / SS, s_ = m % SS;
#pragma unroll
        for (int j = 0; j < 8; j++) {
            int n = n0 + tx * 8 + j;
            int h = n >> 6, d = n & 63;
            outbuf[(((size_t)b_ * NH + h) * SS + s_) * HD + d] = acc[i][j] + bias[n];
        }
    }
}

// ---------------------------------------------------------------------------
// Scores: raw (unnormalized) scores into the probs output region.
// Lower triangle tiles only; per-element k<=q guard on diagonal tiles.
// score = (q . k) / 8 + attention_mask[b, k]
// ---------------------------------------------------------------------------
__global__ __launch_bounds__(256) void scores_kernel(const float* __restrict__ amask,
                                                     float* __restrict__ probs) {
    int kt = blockIdx.x, qt = blockIdx.y, bh = blockIdx.z;
    if (kt > qt) return;
    int b_ = bh / NH;
    const float* Q = g_q + (size_t)bh * SS * HD + (size_t)qt * 64 * HD;
    const float* K = g_k + (size_t)bh * SS * HD + (size_t)kt * 64 * HD;

    __shared__ float Qs[HD][65];
    __shared__ float Ks[HD][65];

    int tid = threadIdx.x;
    int c4 = (tid & 15) * 4;
    int r0 = tid >> 4;
#pragma unroll
    for (int r = 0; r < 4; r++) {
        int row = r0 + r * 16;
        float4 qv = *(const float4*)(Q + (size_t)row * HD + c4);
        Qs[c4 + 0][row] = qv.x; Qs[c4 + 1][row] = qv.y;
        Qs[c4 + 2][row] = qv.z; Qs[c4 + 3][row] = qv.w;
        float4 kv = *(const float4*)(K + (size_t)row * HD + c4);
        Ks[c4 + 0][row] = kv.x; Ks[c4 + 1][row] = kv.y;
        Ks[c4 + 2][row] = kv.z; Ks[c4 + 3][row] = kv.w;
    }
    __syncthreads();

    int tx = tid & 15, ty = tid >> 4;
    float acc[4][4] = {};
#pragma unroll
    for (int dd = 0; dd < HD; dd++) {
        float a[4], b[4];
#pragma unroll
        for (int i = 0; i < 4; i++) a[i] = Qs[dd][ty * 4 + i];
#pragma unroll
        for (int j = 0; j < 4; j++) b[j] = Ks[dd][tx * 4 + j];
#pragma unroll
        for (int i = 0; i < 4; i++)
#pragma unroll
            for (int j = 0; j < 4; j++) acc[i][j] += a[i] * b[j];
    }

    int q0 = qt * 64, k0 = kt * 64;
#pragma unroll
    for (int i = 0; i < 4; i++) {
        int qg = q0 + ty * 4 + i;
        size_t rowbase = ((size_t)bh * SS + qg) * SS;
#pragma unroll
        for (int j = 0; j < 4; j++) {
            int kg = k0 + tx * 4 + j;
            if (kg <= qg)
                probs[rowbase + kg] = acc[i][j] * 0.125f + amask[b_ * SS + kg];
        }
    }
}

// ---------------------------------------------------------------------------
// Row softmax over valid (k<=q) entries; zeros for masked k>q (exact match to
// reference: exp(-1e10 - m) underflows to 0.0f in fp32).
// One block (256 threads) per row, 8 elements per thread.
// ---------------------------------------------------------------------------
__global__ __launch_bounds__(256) void softmax_kernel(float* __restrict__ probs) {
    size_t row = blockIdx.x;
    int q = (int)(row % SS);
    float* p = probs + row * (size_t)SS;
    int nv = q + 1;
    int tid = threadIdx.x;

    float vals[8];
    float mx = -1e30f;
#pragma unroll
    for (int r = 0; r < 8; r++) {
        int k = tid + r * 256;
        vals[r] = (k < nv) ? p[k] : -1e30f;
        mx = fmaxf(mx, vals[r]);
    }
    __shared__ float red[256];
    red[tid] = mx;
    __syncthreads();
    for (int s_ = 128; s_ > 0; s_ >>= 1) {
        if (tid < s_) red[tid] = fmaxf(red[tid], red[tid + s_]);
        __syncthreads();
    }
    mx = red[0];
    __syncthreads();

    float sum = 0.f;
#pragma unroll
    for (int r = 0; r < 8; r++) {
        int k = tid + r * 256;
        float e = (k < nv) ? __expf(vals[r] - mx) : 0.f;
        vals[r] = e;
        sum += e;
    }
    red[tid] = sum;
    __syncthreads();
    for (int s_ = 128; s_ > 0; s_ >>= 1) {
        if (tid < s_) red[tid] += red[tid + s_];
        __syncthreads();
    }
    float inv = __frcp_rn(red[0]);
#pragma unroll
    for (int r = 0; r < 8; r++) {
        int k = tid + r * 256;
        p[k] = vals[r] * inv;
    }
}

// ---------------------------------------------------------------------------
// ctx = probs @ V, lower-triangle k-tiles only.
// Block: 64 queries x 64 dims (full HD). Output to [B,S,NH,HD] (=[B,S,HID]).
// ---------------------------------------------------------------------------
__global__ __launch_bounds__(256) void pv_kernel(const float* __restrict__ probs,
                                                 float* __restrict__ ctx) {
    int qt = blockIdx.x, bh = blockIdx.y;
    int b_ = bh / NH, h = bh % NH;
    const float* V = g_v + (size_t)bh * SS * HD;
    const float* P = probs + ((size_t)bh * SS + (size_t)qt * 64) * SS;

    __shared__ float Ps[64][65];
    __shared__ float Vs[64][65];

    int tid = threadIdx.x;
    int c4 = (tid & 15) * 4;
    int r0 = tid >> 4;
    int tx = tid & 15, ty = tid >> 4;

    float acc[4][4] = {};
    int kmax = (qt + 1) * 64;

    for (int k0 = 0; k0 < kmax; k0 += 64) {
#pragma unroll
        for (int r = 0; r < 4; r++) {
            int row = r0 + r * 16;
            float4 pv = *(const float4*)(P + (size_t)row * SS + k0 + c4);
            Ps[row][c4 + 0] = pv.x; Ps[row][c4 + 1] = pv.y;
            Ps[row][c4 + 2] = pv.z; Ps[row][c4 + 3] = pv.w;
            float4 vv = *(const float4*)(V + (size_t)(k0 + row) * HD + c4);
            Vs[row][c4 + 0] = vv.x; Vs[row][c4 + 1] = vv.y;
            Vs[row][c4 + 2] = vv.z; Vs[row][c4 + 3] = vv.w;
        }
        __syncthreads();
#pragma unroll
        for (int kk = 0; kk < 64; kk++) {
            float a[4], b[4];
#pragma unroll
            for (int i = 0; i < 4; i++) a[i] = Ps[ty * 4 + i][kk];
#pragma unroll
            for (int j = 0; j < 4; j++) b[j] = Vs[kk][tx * 4 + j];
#pragma unroll
            for (int i = 0; i < 4; i++)
#pragma unroll
                for (int j = 0; j < 4; j++) acc[i][j] += a[i] * b[j];
        }
        __syncthreads();
    }

#pragma unroll
    for (int i = 0; i < 4; i++) {
        int qg = qt * 64 + ty * 4 + i;
#pragma unroll
        for (int j = 0; j < 4; j++) {
            int d = tx * 4 + j;
            ctx[(((size_t)b_ * SS + qg) * NH + h) * HD + d] = acc[i][j];
        }
    }
}

// ---------------------------------------------------------------------------
extern "C" void kernel_launch(void* const* d_in, const int* in_sizes, int n_in,
                              void* d_out, int out_size) {
    const float* hidden = (const float*)d_in[0];
    const float* amask  = (const float*)d_in[1];
    const float* Wq = (const float*)d_in[2];
    const float* bq = (const float*)d_in[3];
    const float* Wk = (const float*)d_in[4];
    const float* bk = (const float*)d_in[5];
    const float* Wv = (const float*)d_in[6];
    const float* bv = (const float*)d_in[7];

    float* ctx   = (float*)d_out;
    float* probs = (float*)d_out + CTX_ELEMS;

    dim3 gg(HID / 128, M_TOK / 128);
    qkv_gemm<<<gg, 256>>>(hidden, Wq, bq, 0);
    qkv_gemm<<<gg, 256>>>(hidden, Wk, bk, 1);
    qkv_gemm<<<gg, 256>>>(hidden, Wv, bv, 2);

    scores_kernel<<<dim3(SS / 64, SS / 64, BB * NH), 256>>>(amask, probs);
    softmax_kernel<<<BB * NH * SS, 256>>>(probs);
    pv_kernel<<<dim3(SS / 64, BB * NH), 256>>>(probs, ctx);
}

// round 2
// speedup vs baseline: 1.1104x; 1.1104x over previous
#include <cuda_runtime.h>
#include <math.h>
#include <stdint.h>

#define BB 2
#define SS 2048
#define HID 1024
#define NH 16
#define HD 64
#define M_TOK (BB*SS)                       // 4096
#define CTX_ELEMS ((size_t)BB*SS*HID)       // 4194304

// Scratch for head-split Q,K,V: [B, NH, S, HD]
__device__ float g_q[BB*NH*SS*HD];
__device__ float g_k[BB*NH*SS*HD];
__device__ float g_v[BB*NH*SS*HD];

__device__ __forceinline__ uint32_t f2tf32(float x) {
    uint32_t u;
    asm("cvt.rna.tf32.f32 %0, %1;" : "=r"(u) : "f"(x));
    return u;
}

__device__ __forceinline__ void mma_tf32(float* d, const uint32_t* a, const uint32_t* b) {
    asm volatile(
        "mma.sync.aligned.m16n8k8.row.col.f32.tf32.tf32.f32 "
        "{%0,%1,%2,%3}, {%4,%5,%6,%7}, {%8,%9}, {%0,%1,%2,%3};"
        : "+f"(d[0]), "+f"(d[1]), "+f"(d[2]), "+f"(d[3])
        : "r"(a[0]), "r"(a[1]), "r"(a[2]), "r"(a[3]), "r"(b[0]), "r"(b[1]));
}

// ---------------------------------------------------------------------------
// Fused QKV projection via TF32 tensor cores.
// out[m,n] = sum_k hidden[m,k] * W[n,k] + bias[n], written head-split.
// blockIdx.z in {0,1,2} selects Q/K/V. Tile 128x128, K-stage 32, 8 warps.
// Warp tile 32(m) x 64(n): 2 m16-frags x 8 n8-frags.
// ---------------------------------------------------------------------------
__global__ __launch_bounds__(256) void qkv_mma(const float* __restrict__ A,
    const float* __restrict__ Wq, const float* __restrict__ bq,
    const float* __restrict__ Wk, const float* __restrict__ bk,
    const float* __restrict__ Wv, const float* __restrict__ bv) {
    const float* W    = (blockIdx.z == 0) ? Wq : (blockIdx.z == 1) ? Wk : Wv;
    const float* bias = (blockIdx.z == 0) ? bq : (blockIdx.z == 1) ? bk : bv;
    float* outbuf     = (blockIdx.z == 0) ? g_q : (blockIdx.z == 1) ? g_k : g_v;

    __shared__ uint32_t As[2][32][133];   // [k][m], tf32
    __shared__ uint32_t Ws[2][32][133];   // [k][n], tf32

    int tid = threadIdx.x;
    int m0 = blockIdx.y * 128, n0 = blockIdx.x * 128;
    int lane = tid & 31, w = tid >> 5;
    int wm = (w & 3) * 32;          // warp m offset within tile
    int wn = (w >> 2) * 64;         // warp n offset within tile
    int g = lane >> 2, tig = lane & 3;

    int lrow = tid >> 3;            // 0..31 (+32 steps -> 128 rows)
    int lc4 = (tid & 7) * 4;        // k offset of float4 within stage

    float acc[2][8][4];
#pragma unroll
    for (int i = 0; i < 2; i++)
#pragma unroll
        for (int j = 0; j < 8; j++)
#pragma unroll
            for (int t = 0; t < 4; t++) acc[i][j][t] = 0.f;

    float4 ra[4], rw[4];

    // initial load + store stage 0
#pragma unroll
    for (int r = 0; r < 4; r++) {
        ra[r] = *(const float4*)(A + (size_t)(m0 + lrow + 32 * r) * HID + lc4);
        rw[r] = *(const float4*)(W + (size_t)(n0 + lrow + 32 * r) * HID + lc4);
    }
#pragma unroll
    for (int r = 0; r < 4; r++) {
        int row = lrow + 32 * r;
        As[0][lc4 + 0][row] = f2tf32(ra[r].x);
        As[0][lc4 + 1][row] = f2tf32(ra[r].y);
        As[0][lc4 + 2][row] = f2tf32(ra[r].z);
        As[0][lc4 + 3][row] = f2tf32(ra[r].w);
        Ws[0][lc4 + 0][row] = f2tf32(rw[r].x);
        Ws[0][lc4 + 1][row] = f2tf32(rw[r].y);
        Ws[0][lc4 + 2][row] = f2tf32(rw[r].z);
        Ws[0][lc4 + 3][row] = f2tf32(rw[r].w);
    }
    __syncthreads();

    int buf = 0;
    for (int k0 = 32; k0 <= HID; k0 += 32) {
        bool more = (k0 < HID);
        if (more) {
#pragma unroll
            for (int r = 0; r < 4; r++) {
                ra[r] = *(const float4*)(A + (size_t)(m0 + lrow + 32 * r) * HID + k0 + lc4);
                rw[r] = *(const float4*)(W + (size_t)(n0 + lrow + 32 * r) * HID + k0 + lc4);
            }
        }
        // compute current buffer
#pragma unroll
        for (int ks = 0; ks < 4; ks++) {
            int kb = ks * 8;
            uint32_t a[2][4];
#pragma unroll
            for (int mf = 0; mf < 2; mf++) {
                int m = wm + mf * 16;
                a[mf][0] = As[buf][kb + tig][m + g];
                a[mf][1] = As[buf][kb + tig][m + g + 8];
                a[mf][2] = As[buf][kb + tig + 4][m + g];
                a[mf][3] = As[buf][kb + tig + 4][m + g + 8];
            }
            uint32_t b[8][2];
#pragma unroll
            for (int nf = 0; nf < 8; nf++) {
                int n = wn + nf * 8;
                b[nf][0] = Ws[buf][kb + tig][n + g];
                b[nf][1] = Ws[buf][kb + tig + 4][n + g];
            }
#pragma unroll
            for (int mf = 0; mf < 2; mf++)
#pragma unroll
                for (int nf = 0; nf < 8; nf++)
                    mma_tf32(acc[mf][nf], a[mf], b[nf]);
        }
        if (more) {
            int nb = buf ^ 1;
#pragma unroll
            for (int r = 0; r < 4; r++) {
                int row = lrow + 32 * r;
                As[nb][lc4 + 0][row] = f2tf32(ra[r].x);
                As[nb][lc4 + 1][row] = f2tf32(ra[r].y);
                As[nb][lc4 + 2][row] = f2tf32(ra[r].z);
                As[nb][lc4 + 3][row] = f2tf32(ra[r].w);
                Ws[nb][lc4 + 0][row] = f2tf32(rw[r].x);
                Ws[nb][lc4 + 1][row] = f2tf32(rw[r].y);
                Ws[nb][lc4 + 2][row] = f2tf32(rw[r].z);
                Ws[nb][lc4 + 3][row] = f2tf32(rw[r].w);
            }
        }
        __syncthreads();
        buf ^= 1;
    }

    // epilogue: bias + head-split write
#pragma unroll
    for (int nf = 0; nf < 8; nf++) {
        int c0 = n0 + wn + nf * 8 + tig * 2;
        float bv0 = bias[c0], bv1 = bias[c0 + 1];
        int h = c0 >> 6, d = c0 & 63;
#pragma unroll
        for (int mf = 0; mf < 2; mf++) {
            int r0 = m0 + wm + mf * 16 + g;
#pragma unroll
            for (int half = 0; half < 2; half++) {
                int m = r0 + half * 8;
                int b_ = m >> 11, s_ = m & 2047;
                float2 v;
                v.x = acc[mf][nf][half * 2 + 0] + bv0;
                v.y = acc[mf][nf][half * 2 + 1] + bv1;
                *(float2*)(outbuf + ((((size_t)b_ * NH + h) * SS + s_) << 6) + d) = v;
            }
        }
    }
}

// ---------------------------------------------------------------------------
// Scores via TF32 tensor cores: raw masked scores into probs region.
// 64x64 tile per block, lower-triangle tiles only. 8 warps: warp tile 32x16.
// ---------------------------------------------------------------------------
__global__ __launch_bounds__(256) void scores_mma(const float* __restrict__ amask,
                                                  float* __restrict__ probs) {
    int kt = blockIdx.x, qt = blockIdx.y, bh = blockIdx.z;
    if (kt > qt) return;
    int b_ = bh >> 4;
    const float* Q = g_q + ((size_t)bh * SS + (size_t)qt * 64) * HD;
    const float* K = g_k + ((size_t)bh * SS + (size_t)kt * 64) * HD;

    __shared__ uint32_t Qs[64][69];   // [d][q]
    __shared__ uint32_t Ks[64][69];   // [d][k]

    int tid = threadIdx.x, lane = tid & 31, w = tid >> 5;
    int wq = (w & 1) * 32, wk = (w >> 1) * 16;
    int g = lane >> 2, tig = lane & 3;

    // load+transpose+cvt: row = tid>>2 (64), d = (tid&3)*4 + j*16
    {
        int row = tid >> 2;
        int cbase = (tid & 3) * 4;
#pragma unroll
        for (int j = 0; j < 4; j++) {
            int dcol = cbase + j * 16;
            float4 qv = *(const float4*)(Q + (size_t)row * HD + dcol);
            Qs[dcol + 0][row] = f2tf32(qv.x);
            Qs[dcol + 1][row] = f2tf32(qv.y);
            Qs[dcol + 2][row] = f2tf32(qv.z);
            Qs[dcol + 3][row] = f2tf32(qv.w);
            float4 kv = *(const float4*)(K + (size_t)row * HD + dcol);
            Ks[dcol + 0][row] = f2tf32(kv.x);
            Ks[dcol + 1][row] = f2tf32(kv.y);
            Ks[dcol + 2][row] = f2tf32(kv.z);
            Ks[dcol + 3][row] = f2tf32(kv.w);
        }
    }
    __syncthreads();

    float acc[2][2][4];
#pragma unroll
    for (int i = 0; i < 2; i++)
#pragma unroll
        for (int j = 0; j < 2; j++)
#pragma unroll
            for (int t = 0; t < 4; t++) acc[i][j][t] = 0.f;

#pragma unroll
    for (int ks = 0; ks < 8; ks++) {
        int kb = ks * 8;
        uint32_t a[2][4];
#pragma unroll
        for (int mf = 0; mf < 2; mf++) {
            int m = wq + mf * 16;
            a[mf][0] = Qs[kb + tig][m + g];
            a[mf][1] = Qs[kb + tig][m + g + 8];
            a[mf][2] = Qs[kb + tig + 4][m + g];
            a[mf][3] = Qs[kb + tig + 4][m + g + 8];
        }
        uint32_t b[2][2];
#pragma unroll
        for (int nf = 0; nf < 2; nf++) {
            int n = wk + nf * 8;
            b[nf][0] = Ks[kb + tig][n + g];
            b[nf][1] = Ks[kb + tig + 4][n + g];
        }
#pragma unroll
        for (int mf = 0; mf < 2; mf++)
#pragma unroll
            for (int nf = 0; nf < 2; nf++)
                mma_tf32(acc[mf][nf], a[mf], b[nf]);
    }

    int q0 = qt * 64, k0 = kt * 64;
#pragma unroll
    for (int mf = 0; mf < 2; mf++) {
#pragma unroll
        for (int nf = 0; nf < 2; nf++) {
            int kg0 = k0 + wk + nf * 8 + tig * 2;
            float am0 = amask[b_ * SS + kg0];
            float am1 = amask[b_ * SS + kg0 + 1];
#pragma unroll
            for (int half = 0; half < 2; half++) {
                int qg = q0 + wq + mf * 16 + g + half * 8;
                size_t rowbase = ((size_t)bh * SS + qg) * SS;
                float v0 = acc[mf][nf][half * 2 + 0] * 0.125f + am0;
                float v1 = acc[mf][nf][half * 2 + 1] * 0.125f + am1;
                if (kg0 <= qg)     probs[rowbase + kg0] = v0;
                if (kg0 + 1 <= qg) probs[rowbase + kg0 + 1] = v1;
            }
        }
    }
}

// ---------------------------------------------------------------------------
// Row softmax over valid (k<=q) entries; zeros for masked k>q.
// ---------------------------------------------------------------------------
__global__ __launch_bounds__(256) void softmax_kernel(float* __restrict__ probs) {
    size_t row = blockIdx.x;
    int q = (int)(row % SS);
    float* p = probs + row * (size_t)SS;
    int nv = q + 1;
    int tid = threadIdx.x;

    float vals[8];
    float mx = -1e30f;
#pragma unroll
    for (int r = 0; r < 8; r++) {
        int k = tid + r * 256;
        vals[r] = (k < nv) ? p[k] : -1e30f;
        mx = fmaxf(mx, vals[r]);
    }
    __shared__ float red[256];
    red[tid] = mx;
    __syncthreads();
    for (int s_ = 128; s_ > 0; s_ >>= 1) {
        if (tid < s_) red[tid] = fmaxf(red[tid], red[tid + s_]);
        __syncthreads();
    }
    mx = red[0];
    __syncthreads();

    float sum = 0.f;
#pragma unroll
    for (int r = 0; r < 8; r++) {
        int k = tid + r * 256;
        float e = (k < nv) ? __expf(vals[r] - mx) : 0.f;
        vals[r] = e;
        sum += e;
    }
    red[tid] = sum;
    __syncthreads();
    for (int s_ = 128; s_ > 0; s_ >>= 1) {
        if (tid < s_) red[tid] += red[tid + s_];
        __syncthreads();
    }
    float inv = __frcp_rn(red[0]);
#pragma unroll
    for (int r = 0; r < 8; r++) {
        int k = tid + r * 256;
        p[k] = vals[r] * inv;
    }
}

// ---------------------------------------------------------------------------
// ctx = probs @ V, lower-triangle k-tiles only (fp32 FFMA, unchanged).
// ---------------------------------------------------------------------------
__global__ __launch_bounds__(256) void pv_kernel(const float* __restrict__ probs,
                                                 float* __restrict__ ctx) {
    int qt = blockIdx.x, bh = blockIdx.y;
    int b_ = bh / NH, h = bh % NH;
    const float* V = g_v + (size_t)bh * SS * HD;
    const float* P = probs + ((size_t)bh * SS + (size_t)qt * 64) * SS;

    __shared__ float Ps[64][65];
    __shared__ float Vs[64][65];

    int tid = threadIdx.x;
    int c4 = (tid & 15) * 4;
    int r0 = tid >> 4;
    int tx = tid & 15, ty = tid >> 4;

    float acc[4][4] = {};
    int kmax = (qt + 1) * 64;

    for (int k0 = 0; k0 < kmax; k0 += 64) {
#pragma unroll
        for (int r = 0; r < 4; r++) {
            int row = r0 + r * 16;
            float4 pv = *(const float4*)(P + (size_t)row * SS + k0 + c4);
            Ps[row][c4 + 0] = pv.x; Ps[row][c4 + 1] = pv.y;
            Ps[row][c4 + 2] = pv.z; Ps[row][c4 + 3] = pv.w;
            float4 vv = *(const float4*)(V + (size_t)(k0 + row) * HD + c4);
            Vs[row][c4 + 0] = vv.x; Vs[row][c4 + 1] = vv.y;
            Vs[row][c4 + 2] = vv.z; Vs[row][c4 + 3] = vv.w;
        }
        __syncthreads();
#pragma unroll
        for (int kk = 0; kk < 64; kk++) {
            float a[4], b[4];
#pragma unroll
            for (int i = 0; i < 4; i++) a[i] = Ps[ty * 4 + i][kk];
#pragma unroll
            for (int j = 0; j < 4; j++) b[j] = Vs[kk][tx * 4 + j];
#pragma unroll
            for (int i = 0; i < 4; i++)
#pragma unroll
                for (int j = 0; j < 4; j++) acc[i][j] += a[i] * b[j];
        }
        __syncthreads();
    }

#pragma unroll
    for (int i = 0; i < 4; i++) {
        int qg = qt * 64 + ty * 4 + i;
#pragma unroll
        for (int j = 0; j < 4; j++) {
            int d = tx * 4 + j;
            ctx[(((size_t)b_ * SS + qg) * NH + h) * HD + d] = acc[i][j];
        }
    }
}

// ---------------------------------------------------------------------------
extern "C" void kernel_launch(void* const* d_in, const int* in_sizes, int n_in,
                              void* d_out, int out_size) {
    const float* hidden = (const float*)d_in[0];
    const float* amask  = (const float*)d_in[1];
    const float* Wq = (const float*)d_in[2];
    const float* bq = (const float*)d_in[3];
    const float* Wk = (const float*)d_in[4];
    const float* bk = (const float*)d_in[5];
    const float* Wv = (const float*)d_in[6];
    const float* bv = (const float*)d_in[7];

    float* ctx   = (float*)d_out;
    float* probs = (float*)d_out + CTX_ELEMS;

    dim3 gq(HID / 128, M_TOK / 128, 3);
    qkv_mma<<<gq, 256>>>(hidden, Wq, bq, Wk, bk, Wv, bv);

    scores_mma<<<dim3(SS / 64, SS / 64, BB * NH), 256>>>(amask, probs);
    softmax_kernel<<<BB * NH * SS, 256>>>(probs);
    pv_kernel<<<dim3(SS / 64, BB * NH), 256>>>(probs, ctx);
}

// round 3
// speedup vs baseline: 2.1128x; 1.9028x over previous
#include <cuda_runtime.h>
#include <math.h>
#include <stdint.h>

#define BB 2
#define SS 2048
#define HID 1024
#define NH 16
#define HD 64
#define M_TOK (BB*SS)                       // 4096
#define CTX_ELEMS ((size_t)BB*SS*HID)       // 4194304

// Scratch for head-split Q,K,V: [B, NH, S, HD]
__device__ float g_q[BB*NH*SS*HD];
__device__ float g_k[BB*NH*SS*HD];
__device__ float g_v[BB*NH*SS*HD];

__device__ __forceinline__ uint32_t f2tf32(float x) {
    uint32_t u;
    asm("cvt.rna.tf32.f32 %0, %1;" : "=r"(u) : "f"(x));
    return u;
}

__device__ __forceinline__ void mma_tf32(float* d, const uint32_t* a, const uint32_t* b) {
    asm volatile(
        "mma.sync.aligned.m16n8k8.row.col.f32.tf32.tf32.f32 "
        "{%0,%1,%2,%3}, {%4,%5,%6,%7}, {%8,%9}, {%0,%1,%2,%3};"
        : "+f"(d[0]), "+f"(d[1]), "+f"(d[2]), "+f"(d[3])
        : "r"(a[0]), "r"(a[1]), "r"(a[2]), "r"(a[3]), "r"(b[0]), "r"(b[1]));
}

// ---------------------------------------------------------------------------
// Fused QKV projection via TF32 tensor cores.
// ---------------------------------------------------------------------------
__global__ __launch_bounds__(256) void qkv_mma(const float* __restrict__ A,
    const float* __restrict__ Wq, const float* __restrict__ bq,
    const float* __restrict__ Wk, const float* __restrict__ bk,
    const float* __restrict__ Wv, const float* __restrict__ bv) {
    const float* W    = (blockIdx.z == 0) ? Wq : (blockIdx.z == 1) ? Wk : Wv;
    const float* bias = (blockIdx.z == 0) ? bq : (blockIdx.z == 1) ? bk : bv;
    float* outbuf     = (blockIdx.z == 0) ? g_q : (blockIdx.z == 1) ? g_k : g_v;

    __shared__ uint32_t As[2][32][133];   // [k][m], tf32
    __shared__ uint32_t Ws[2][32][133];   // [k][n], tf32

    int tid = threadIdx.x;
    int m0 = blockIdx.y * 128, n0 = blockIdx.x * 128;
    int lane = tid & 31, w = tid >> 5;
    int wm = (w & 3) * 32;
    int wn = (w >> 2) * 64;
    int g = lane >> 2, tig = lane & 3;

    int lrow = tid >> 3;
    int lc4 = (tid & 7) * 4;

    float acc[2][8][4];
#pragma unroll
    for (int i = 0; i < 2; i++)
#pragma unroll
        for (int j = 0; j < 8; j++)
#pragma unroll
            for (int t = 0; t < 4; t++) acc[i][j][t] = 0.f;

    float4 ra[4], rw[4];

#pragma unroll
    for (int r = 0; r < 4; r++) {
        ra[r] = *(const float4*)(A + (size_t)(m0 + lrow + 32 * r) * HID + lc4);
        rw[r] = *(const float4*)(W + (size_t)(n0 + lrow + 32 * r) * HID + lc4);
    }
#pragma unroll
    for (int r = 0; r < 4; r++) {
        int row = lrow + 32 * r;
        As[0][lc4 + 0][row] = f2tf32(ra[r].x);
        As[0][lc4 + 1][row] = f2tf32(ra[r].y);
        As[0][lc4 + 2][row] = f2tf32(ra[r].z);
        As[0][lc4 + 3][row] = f2tf32(ra[r].w);
        Ws[0][lc4 + 0][row] = f2tf32(rw[r].x);
        Ws[0][lc4 + 1][row] = f2tf32(rw[r].y);
        Ws[0][lc4 + 2][row] = f2tf32(rw[r].z);
        Ws[0][lc4 + 3][row] = f2tf32(rw[r].w);
    }
    __syncthreads();

    int buf = 0;
    for (int k0 = 32; k0 <= HID; k0 += 32) {
        bool more = (k0 < HID);
        if (more) {
#pragma unroll
            for (int r = 0; r < 4; r++) {
                ra[r] = *(const float4*)(A + (size_t)(m0 + lrow + 32 * r) * HID + k0 + lc4);
                rw[r] = *(const float4*)(W + (size_t)(n0 + lrow + 32 * r) * HID + k0 + lc4);
            }
        }
#pragma unroll
        for (int ks = 0; ks < 4; ks++) {
            int kb = ks * 8;
            uint32_t a[2][4];
#pragma unroll
            for (int mf = 0; mf < 2; mf++) {
                int m = wm + mf * 16;
                a[mf][0] = As[buf][kb + tig][m + g];
                a[mf][1] = As[buf][kb + tig][m + g + 8];
                a[mf][2] = As[buf][kb + tig + 4][m + g];
                a[mf][3] = As[buf][kb + tig + 4][m + g + 8];
            }
            uint32_t b[8][2];
#pragma unroll
            for (int nf = 0; nf < 8; nf++) {
                int n = wn + nf * 8;
                b[nf][0] = Ws[buf][kb + tig][n + g];
                b[nf][1] = Ws[buf][kb + tig + 4][n + g];
            }
#pragma unroll
            for (int mf = 0; mf < 2; mf++)
#pragma unroll
                for (int nf = 0; nf < 8; nf++)
                    mma_tf32(acc[mf][nf], a[mf], b[nf]);
        }
        if (more) {
            int nb = buf ^ 1;
#pragma unroll
            for (int r = 0; r < 4; r++) {
                int row = lrow + 32 * r;
                As[nb][lc4 + 0][row] = f2tf32(ra[r].x);
                As[nb][lc4 + 1][row] = f2tf32(ra[r].y);
                As[nb][lc4 + 2][row] = f2tf32(ra[r].z);
                As[nb][lc4 + 3][row] = f2tf32(ra[r].w);
                Ws[nb][lc4 + 0][row] = f2tf32(rw[r].x);
                Ws[nb][lc4 + 1][row] = f2tf32(rw[r].y);
                Ws[nb][lc4 + 2][row] = f2tf32(rw[r].z);
                Ws[nb][lc4 + 3][row] = f2tf32(rw[r].w);
            }
        }
        __syncthreads();
        buf ^= 1;
    }

#pragma unroll
    for (int nf = 0; nf < 8; nf++) {
        int c0 = n0 + wn + nf * 8 + tig * 2;
        float bv0 = bias[c0], bv1 = bias[c0 + 1];
        int h = c0 >> 6, d = c0 & 63;
#pragma unroll
        for (int mf = 0; mf < 2; mf++) {
            int r0 = m0 + wm + mf * 16 + g;
#pragma unroll
            for (int half = 0; half < 2; half++) {
                int m = r0 + half * 8;
                int b_ = m >> 11, s_ = m & 2047;
                float2 v;
                v.x = acc[mf][nf][half * 2 + 0] + bv0;
                v.y = acc[mf][nf][half * 2 + 1] + bv1;
                *(float2*)(outbuf + ((((size_t)b_ * NH + h) * SS + s_) << 6) + d) = v;
            }
        }
    }
}

// ---------------------------------------------------------------------------
// Scores via TF32 tensor cores: raw masked scores into probs region.
// ---------------------------------------------------------------------------
__global__ __launch_bounds__(256) void scores_mma(const float* __restrict__ amask,
                                                  float* __restrict__ probs) {
    int kt = blockIdx.x, qt = blockIdx.y, bh = blockIdx.z;
    if (kt > qt) return;
    int b_ = bh >> 4;
    const float* Q = g_q + ((size_t)bh * SS + (size_t)qt * 64) * HD;
    const float* K = g_k + ((size_t)bh * SS + (size_t)kt * 64) * HD;

    __shared__ uint32_t Qs[64][69];   // [d][q]
    __shared__ uint32_t Ks[64][69];   // [d][k]

    int tid = threadIdx.x, lane = tid & 31, w = tid >> 5;
    int wq = (w & 1) * 32, wk = (w >> 1) * 16;
    int g = lane >> 2, tig = lane & 3;

    {
        int row = tid >> 2;
        int cbase = (tid & 3) * 4;
#pragma unroll
        for (int j = 0; j < 4; j++) {
            int dcol = cbase + j * 16;
            float4 qv = *(const float4*)(Q + (size_t)row * HD + dcol);
            Qs[dcol + 0][row] = f2tf32(qv.x);
            Qs[dcol + 1][row] = f2tf32(qv.y);
            Qs[dcol + 2][row] = f2tf32(qv.z);
            Qs[dcol + 3][row] = f2tf32(qv.w);
            float4 kv = *(const float4*)(K + (size_t)row * HD + dcol);
            Ks[dcol + 0][row] = f2tf32(kv.x);
            Ks[dcol + 1][row] = f2tf32(kv.y);
            Ks[dcol + 2][row] = f2tf32(kv.z);
            Ks[dcol + 3][row] = f2tf32(kv.w);
        }
    }
    __syncthreads();

    float acc[2][2][4];
#pragma unroll
    for (int i = 0; i < 2; i++)
#pragma unroll
        for (int j = 0; j < 2; j++)
#pragma unroll
            for (int t = 0; t < 4; t++) acc[i][j][t] = 0.f;

#pragma unroll
    for (int ks = 0; ks < 8; ks++) {
        int kb = ks * 8;
        uint32_t a[2][4];
#pragma unroll
        for (int mf = 0; mf < 2; mf++) {
            int m = wq + mf * 16;
            a[mf][0] = Qs[kb + tig][m + g];
            a[mf][1] = Qs[kb + tig][m + g + 8];
            a[mf][2] = Qs[kb + tig + 4][m + g];
            a[mf][3] = Qs[kb + tig + 4][m + g + 8];
        }
        uint32_t b[2][2];
#pragma unroll
        for (int nf = 0; nf < 2; nf++) {
            int n = wk + nf * 8;
            b[nf][0] = Ks[kb + tig][n + g];
            b[nf][1] = Ks[kb + tig + 4][n + g];
        }
#pragma unroll
        for (int mf = 0; mf < 2; mf++)
#pragma unroll
            for (int nf = 0; nf < 2; nf++)
                mma_tf32(acc[mf][nf], a[mf], b[nf]);
    }

    int q0 = qt * 64, k0 = kt * 64;
#pragma unroll
    for (int mf = 0; mf < 2; mf++) {
#pragma unroll
        for (int nf = 0; nf < 2; nf++) {
            int kg0 = k0 + wk + nf * 8 + tig * 2;
            float am0 = amask[b_ * SS + kg0];
            float am1 = amask[b_ * SS + kg0 + 1];
#pragma unroll
            for (int half = 0; half < 2; half++) {
                int qg = q0 + wq + mf * 16 + g + half * 8;
                size_t rowbase = ((size_t)bh * SS + qg) * SS;
                float v0 = acc[mf][nf][half * 2 + 0] * 0.125f + am0;
                float v1 = acc[mf][nf][half * 2 + 1] * 0.125f + am1;
                if (kg0 <= qg)     probs[rowbase + kg0] = v0;
                if (kg0 + 1 <= qg) probs[rowbase + kg0 + 1] = v1;
            }
        }
    }
}

// ---------------------------------------------------------------------------
// Row softmax over valid (k<=q) entries; zeros for masked k>q.
// ---------------------------------------------------------------------------
__global__ __launch_bounds__(256) void softmax_kernel(float* __restrict__ probs) {
    size_t row = blockIdx.x;
    int q = (int)(row % SS);
    float* p = probs + row * (size_t)SS;
    int nv = q + 1;
    int tid = threadIdx.x;

    float vals[8];
    float mx = -1e30f;
#pragma unroll
    for (int r = 0; r < 8; r++) {
        int k = tid + r * 256;
        vals[r] = (k < nv) ? p[k] : -1e30f;
        mx = fmaxf(mx, vals[r]);
    }
    __shared__ float red[256];
    red[tid] = mx;
    __syncthreads();
    for (int s_ = 128; s_ > 0; s_ >>= 1) {
        if (tid < s_) red[tid] = fmaxf(red[tid], red[tid + s_]);
        __syncthreads();
    }
    mx = red[0];
    __syncthreads();

    float sum = 0.f;
#pragma unroll
    for (int r = 0; r < 8; r++) {
        int k = tid + r * 256;
        float e = (k < nv) ? __expf(vals[r] - mx) : 0.f;
        vals[r] = e;
        sum += e;
    }
    red[tid] = sum;
    __syncthreads();
    for (int s_ = 128; s_ > 0; s_ >>= 1) {
        if (tid < s_) red[tid] += red[tid + s_];
        __syncthreads();
    }
    float inv = __frcp_rn(red[0]);
#pragma unroll
    for (int r = 0; r < 8; r++) {
        int k = tid + r * 256;
        p[k] = vals[r] * inv;
    }
}

// ---------------------------------------------------------------------------
// ctx = probs @ V via TF32 tensor cores, lower-triangle k-tiles only.
// Block: 64 q x 64 d (full HD). 8 warps, warp tile 32x16.
// A = P (q x k) stored transposed in smem [k][q]; B = V (k x d) stored [k][d]
// (mma col-major B == V's natural layout). Diagonal-tile upper triangle holds
// exact softmax zeros, so full tiles are safe.
// ---------------------------------------------------------------------------
__global__ __launch_bounds__(256) void pv_mma(const float* __restrict__ probs,
                                              float* __restrict__ ctx) {
    int qt = blockIdx.x, bh = blockIdx.y;
    int b_ = bh >> 4, h = bh & 15;
    const float* V = g_v + (size_t)bh * SS * HD;
    const float* P = probs + ((size_t)bh * SS + (size_t)qt * 64) * SS;

    __shared__ uint32_t Ps[64][69];   // [k][q]
    __shared__ uint32_t Vs[64][69];   // [k][d]

    int tid = threadIdx.x, lane = tid & 31, w = tid >> 5;
    int wq = (w & 1) * 32, wd = (w >> 1) * 16;
    int g = lane >> 2, tig = lane & 3;

    int row = tid >> 2;               // 0..63
    int cbase = (tid & 3) * 4;        // {0,4,8,12}

    float acc[2][2][4];
#pragma unroll
    for (int i = 0; i < 2; i++)
#pragma unroll
        for (int j = 0; j < 2; j++)
#pragma unroll
            for (int t = 0; t < 4; t++) acc[i][j][t] = 0.f;

    int ntiles = qt + 1;
    for (int t = 0; t < ntiles; t++) {
        int k0 = t * 64;
#pragma unroll
        for (int j = 0; j < 4; j++) {
            int col = cbase + j * 16;
            // P[q=row][k0+col..+3] -> Ps[col][row] (transpose)
            float4 pv = *(const float4*)(P + (size_t)row * SS + k0 + col);
            Ps[col + 0][row] = f2tf32(pv.x);
            Ps[col + 1][row] = f2tf32(pv.y);
            Ps[col + 2][row] = f2tf32(pv.z);
            Ps[col + 3][row] = f2tf32(pv.w);
            // V[k0+row][col..+3] -> Vs[row][col] (direct)
            float4 vv = *(const float4*)(V + (size_t)(k0 + row) * HD + col);
            Vs[row][col + 0] = f2tf32(vv.x);
            Vs[row][col + 1] = f2tf32(vv.y);
            Vs[row][col + 2] = f2tf32(vv.z);
            Vs[row][col + 3] = f2tf32(vv.w);
        }
        __syncthreads();

#pragma unroll
        for (int ks = 0; ks < 8; ks++) {
            int kb = ks * 8;
            uint32_t a[2][4];
#pragma unroll
            for (int mf = 0; mf < 2; mf++) {
                int m = wq + mf * 16;
                a[mf][0] = Ps[kb + tig][m + g];
                a[mf][1] = Ps[kb + tig][m + g + 8];
                a[mf][2] = Ps[kb + tig + 4][m + g];
                a[mf][3] = Ps[kb + tig + 4][m + g + 8];
            }
            uint32_t b[2][2];
#pragma unroll
            for (int nf = 0; nf < 2; nf++) {
                int n = wd + nf * 8;
                b[nf][0] = Vs[kb + tig][n + g];
                b[nf][1] = Vs[kb + tig + 4][n + g];
            }
#pragma unroll
            for (int mf = 0; mf < 2; mf++)
#pragma unroll
                for (int nf = 0; nf < 2; nf++)
                    mma_tf32(acc[mf][nf], a[mf], b[nf]);
        }
        __syncthreads();
    }

    int q0 = qt * 64;
#pragma unroll
    for (int mf = 0; mf < 2; mf++) {
#pragma unroll
        for (int nf = 0; nf < 2; nf++) {
            int d0 = wd + nf * 8 + tig * 2;
#pragma unroll
            for (int half = 0; half < 2; half++) {
                int qg = q0 + wq + mf * 16 + g + half * 8;
                float2 v;
                v.x = acc[mf][nf][half * 2 + 0];
                v.y = acc[mf][nf][half * 2 + 1];
                *(float2*)(ctx + (((size_t)b_ * SS + qg) * NH + h) * HD + d0) = v;
            }
        }
    }
}

// ---------------------------------------------------------------------------
extern "C" void kernel_launch(void* const* d_in, const int* in_sizes, int n_in,
                              void* d_out, int out_size) {
    const float* hidden = (const float*)d_in[0];
    const float* amask  = (const float*)d_in[1];
    const float* Wq = (const float*)d_in[2];
    const float* bq = (const float*)d_in[3];
    const float* Wk = (const float*)d_in[4];
    const float* bk = (const float*)d_in[5];
    const float* Wv = (const float*)d_in[6];
    const float* bv = (const float*)d_in[7];

    float* ctx   = (float*)d_out;
    float* probs = (float*)d_out + CTX_ELEMS;

    dim3 gq(HID / 128, M_TOK / 128, 3);
    qkv_mma<<<gq, 256>>>(hidden, Wq, bq, Wk, bk, Wv, bv);

    scores_mma<<<dim3(SS / 64, SS / 64, BB * NH), 256>>>(amask, probs);
    softmax_kernel<<<BB * NH * SS, 256>>>(probs);
    pv_mma<<<dim3(SS / 64, BB * NH), 256>>>(probs, ctx);
}